// round 1
// baseline (speedup 1.0000x reference)
#include <cuda_runtime.h>
#include <math.h>

#define B_    2
#define T_    2048
#define C_    2048
#define H_    16
#define HKV_  4
#define REP_  4
#define HD_   128
#define KVD_  512
#define QKVN_ 3072          // C + 2*KV_DIM
#define EPS_  1.1920929e-07f

// ---------------- scratch (static device allocations are allowed) ----------
__device__ float g_xn[(size_t)B_ * T_ * C_];       // rmsnorm(x)
__device__ float g_qkv[(size_t)B_ * T_ * QKVN_];   // qkv projection
__device__ float g_q[(size_t)B_ * H_ * T_ * HD_];  // [B,H,T,HD] post norm/rope/gain
__device__ float g_k[(size_t)B_ * HKV_ * T_ * HD_];
__device__ float g_v[(size_t)B_ * HKV_ * T_ * HD_];
__device__ float g_ao[(size_t)B_ * T_ * C_];       // attention out [B,T,C]
__device__ float g_cos[T_ * 64];
__device__ float g_sin[T_ * 64];

// ---------------- RoPE tables (double-precision trig, fast-math immune) ----
__global__ void k_rope() {
    int t = blockIdx.x;
    int j = threadIdx.x;  // 0..63
    float invf = 1.0f / powf(10000.0f, (2.0f * (float)j) / 128.0f);
    float ang  = (float)t * invf;   // matches fp32 outer() in reference
    g_cos[t * 64 + j] = (float)cos((double)ang);
    g_sin[t * 64 + j] = (float)sin((double)ang);
}

// ---------------- input RMSNorm over C=2048, one block per row -------------
__global__ void __launch_bounds__(256) k_rmsnorm(const float* __restrict__ x) {
    int row = blockIdx.x;                        // 0..B*T-1
    const float* xr = x + (size_t)row * C_;
    float ss = 0.f;
    for (int i = threadIdx.x; i < C_; i += 256) {
        float v = xr[i];
        ss = fmaf(v, v, ss);
    }
    __shared__ float sh[8];
    int lane = threadIdx.x & 31, wid = threadIdx.x >> 5;
#pragma unroll
    for (int o = 16; o; o >>= 1) ss += __shfl_xor_sync(0xffffffffu, ss, o);
    if (lane == 0) sh[wid] = ss;
    __syncthreads();
    float tot = (threadIdx.x < 8) ? sh[threadIdx.x] : 0.f;
    if (wid == 0) {
#pragma unroll
        for (int o = 16; o; o >>= 1) tot += __shfl_xor_sync(0xffffffffu, tot, o);
    }
    __shared__ float sb;
    if (threadIdx.x == 0) sb = tot;
    __syncthreads();
    float sc = rsqrtf(sb * (1.0f / C_) + EPS_);
    for (int i = threadIdx.x; i < C_; i += 256)
        g_xn[(size_t)row * C_ + i] = xr[i] * sc;
}

// ---------------- classic fp32 SGEMM: C[M,N] = A[M,K] @ B[K,N] -------------
// 128x128 block tile, BK=16, 256 threads, 8x8 per thread. All dims divisible.
__global__ void __launch_bounds__(256) k_sgemm(const float* __restrict__ A,
                                               const float* __restrict__ Bm,
                                               float* __restrict__ Cm,
                                               int M, int N, int K) {
    __shared__ __align__(16) float As[16][128];
    __shared__ __align__(16) float Bs[16][128];
    int tid = threadIdx.x;
    int tx = tid & 15, ty = tid >> 4;
    int m0 = blockIdx.y * 128, n0 = blockIdx.x * 128;
    float acc[8][8] = {};
    for (int k0 = 0; k0 < K; k0 += 16) {
        // load A tile (128x16), store transposed As[k][m]
#pragma unroll
        for (int s = 0; s < 2; s++) {
            int idx = tid + s * 256;          // 0..511 float4 slots
            int r = idx >> 2;                 // 0..127
            int c4 = idx & 3;                 // 0..3
            float4 a = *(const float4*)(A + (size_t)(m0 + r) * K + k0 + c4 * 4);
            As[c4 * 4 + 0][r] = a.x;
            As[c4 * 4 + 1][r] = a.y;
            As[c4 * 4 + 2][r] = a.z;
            As[c4 * 4 + 3][r] = a.w;
        }
        // load B tile (16x128)
#pragma unroll
        for (int s = 0; s < 2; s++) {
            int idx = tid + s * 256;
            int r = idx >> 5;                 // 0..15
            int c4 = idx & 31;                // 0..31
            *(float4*)(&Bs[r][c4 * 4]) =
                *(const float4*)(Bm + (size_t)(k0 + r) * N + n0 + c4 * 4);
        }
        __syncthreads();
#pragma unroll
        for (int kk = 0; kk < 16; kk++) {
            float a[8], b[8];
            float4 a0 = *(float4*)(&As[kk][ty * 8]);
            float4 a1 = *(float4*)(&As[kk][ty * 8 + 4]);
            float4 b0 = *(float4*)(&Bs[kk][tx * 8]);
            float4 b1 = *(float4*)(&Bs[kk][tx * 8 + 4]);
            a[0]=a0.x;a[1]=a0.y;a[2]=a0.z;a[3]=a0.w;a[4]=a1.x;a[5]=a1.y;a[6]=a1.z;a[7]=a1.w;
            b[0]=b0.x;b[1]=b0.y;b[2]=b0.z;b[3]=b0.w;b[4]=b1.x;b[5]=b1.y;b[6]=b1.z;b[7]=b1.w;
#pragma unroll
            for (int i = 0; i < 8; i++)
#pragma unroll
                for (int j = 0; j < 8; j++)
                    acc[i][j] = fmaf(a[i], b[j], acc[i][j]);
        }
        __syncthreads();
    }
#pragma unroll
    for (int i = 0; i < 8; i++) {
        float* crow = Cm + (size_t)(m0 + ty * 8 + i) * N + n0 + tx * 8;
        *(float4*)(crow)     = make_float4(acc[i][0], acc[i][1], acc[i][2], acc[i][3]);
        *(float4*)(crow + 4) = make_float4(acc[i][4], acc[i][5], acc[i][6], acc[i][7]);
    }
}

// ---------------- Q/K rmsnorm + RoPE + gain; V scatter. One warp per row ---
__global__ void __launch_bounds__(256) k_qkpost(const float* __restrict__ qg) {
    int gwarp = (blockIdx.x * 256 + threadIdx.x) >> 5;
    int lane = threadIdx.x & 31;
    const int NQ = B_ * T_ * H_;   // 65536
    const int NK = B_ * T_ * HKV_; // 16384
    if (gwarp < NQ) {
        int h = gwarp % H_;
        int bt = gwarp / H_;
        int t = bt % T_, b = bt / T_;
        const float* src = g_qkv + (size_t)bt * QKVN_ + h * HD_;
        float v0 = src[lane], v1 = src[lane + 32], v2 = src[lane + 64], v3 = src[lane + 96];
        float ss = v0 * v0 + v1 * v1 + v2 * v2 + v3 * v3;
#pragma unroll
        for (int o = 16; o; o >>= 1) ss += __shfl_xor_sync(0xffffffffu, ss, o);
        float sc = rsqrtf(ss * (1.0f / HD_) + EPS_);
        v0 *= sc; v1 *= sc; v2 *= sc; v3 *= sc;
        float c0 = g_cos[t * 64 + lane],      s0 = g_sin[t * 64 + lane];
        float c1 = g_cos[t * 64 + 32 + lane], s1 = g_sin[t * 64 + 32 + lane];
        float r0 = v0 * c0 - v2 * s0;
        float r1 = v1 * c1 - v3 * s1;
        float r2 = v2 * c0 + v0 * s0;
        float r3 = v3 * c1 + v1 * s1;
        float gn = qg[h];
        float* dst = g_q + ((size_t)(b * H_ + h) * T_ + t) * HD_;
        dst[lane] = r0 * gn; dst[lane + 32] = r1 * gn;
        dst[lane + 64] = r2 * gn; dst[lane + 96] = r3 * gn;
    } else if (gwarp < NQ + NK) {
        int w = gwarp - NQ;
        int g = w % HKV_;
        int bt = w / HKV_;
        int t = bt % T_, b = bt / T_;
        const float* src = g_qkv + (size_t)bt * QKVN_ + C_ + g * HD_;
        float v0 = src[lane], v1 = src[lane + 32], v2 = src[lane + 64], v3 = src[lane + 96];
        float ss = v0 * v0 + v1 * v1 + v2 * v2 + v3 * v3;
#pragma unroll
        for (int o = 16; o; o >>= 1) ss += __shfl_xor_sync(0xffffffffu, ss, o);
        float sc = rsqrtf(ss * (1.0f / HD_) + EPS_);
        v0 *= sc; v1 *= sc; v2 *= sc; v3 *= sc;
        float c0 = g_cos[t * 64 + lane],      s0 = g_sin[t * 64 + lane];
        float c1 = g_cos[t * 64 + 32 + lane], s1 = g_sin[t * 64 + 32 + lane];
        float r0 = v0 * c0 - v2 * s0;
        float r1 = v1 * c1 - v3 * s1;
        float r2 = v2 * c0 + v0 * s0;
        float r3 = v3 * c1 + v1 * s1;
        float* dst = g_k + ((size_t)(b * HKV_ + g) * T_ + t) * HD_;
        dst[lane] = r0; dst[lane + 32] = r1; dst[lane + 64] = r2; dst[lane + 96] = r3;
    } else if (gwarp < NQ + 2 * NK) {
        int w = gwarp - NQ - NK;
        int g = w % HKV_;
        int bt = w / HKV_;
        int t = bt % T_, b = bt / T_;
        const float* src = g_qkv + (size_t)bt * QKVN_ + C_ + KVD_ + g * HD_;
        float* dst = g_v + ((size_t)(b * HKV_ + g) * T_ + t) * HD_;
        dst[lane] = src[lane]; dst[lane + 32] = src[lane + 32];
        dst[lane + 64] = src[lane + 64]; dst[lane + 96] = src[lane + 96];
    }
}

// ---------------- causal flash attention, fp32, 64x64 tiles ----------------
#define FA_BM 64
#define FA_BN 64
#define SQS 129
#define SKS 129
#define SVS 132
#define SPS 68
#define FA_SMEM ((FA_BM * SQS + FA_BN * SKS + FA_BN * SVS + FA_BM * SPS) * 4)

__global__ void __launch_bounds__(256) k_flash() {
    extern __shared__ float sm[];
    float* sQ = sm;                       // 64 x 129
    float* sK = sQ + FA_BM * SQS;         // 64 x 129
    float* sV = sK + FA_BN * SKS;         // 64 x 132
    float* sP = sV + FA_BN * SVS;         // 64 x 68

    int tid = threadIdx.x;
    int tx = tid & 15, ty = tid >> 4;     // 16 x 16
    int qt = blockIdx.x;
    int h = blockIdx.y;
    int b = blockIdx.z;
    int g = h >> 2;                       // kv head
    int q0 = qt * FA_BM;

    const float* Q = g_q + ((size_t)(b * H_ + h) * T_ + q0) * HD_;
    const float* K = g_k + (size_t)(b * HKV_ + g) * T_ * HD_;
    const float* V = g_v + (size_t)(b * HKV_ + g) * T_ * HD_;

    // load Q tile (64 x 128)
#pragma unroll
    for (int s = 0; s < 8; s++) {
        int idx = tid + s * 256;          // float4 slot 0..2047
        int r = idx >> 5;
        int c = (idx & 31) * 4;
        float4 qv = *(const float4*)(Q + (size_t)r * HD_ + c);
        sQ[r * SQS + c]     = qv.x;
        sQ[r * SQS + c + 1] = qv.y;
        sQ[r * SQS + c + 2] = qv.z;
        sQ[r * SQS + c + 3] = qv.w;
    }

    float m[4], l[4], o[4][8];
#pragma unroll
    for (int i = 0; i < 4; i++) {
        m[i] = -INFINITY; l[i] = 0.f;
#pragma unroll
        for (int c = 0; c < 8; c++) o[i][c] = 0.f;
    }

    const float scale = 0.08838834764831845f;  // 1/sqrt(128)
    int kend = q0 + FA_BM;

    for (int ks = 0; ks < kend; ks += FA_BN) {
        __syncthreads();   // previous O-update done before overwriting K/V
#pragma unroll
        for (int s = 0; s < 8; s++) {
            int idx = tid + s * 256;
            int r = idx >> 5;
            int c = (idx & 31) * 4;
            float4 kv = *(const float4*)(K + (size_t)(ks + r) * HD_ + c);
            sK[r * SKS + c]     = kv.x;
            sK[r * SKS + c + 1] = kv.y;
            sK[r * SKS + c + 2] = kv.z;
            sK[r * SKS + c + 3] = kv.w;
            float4 vv = *(const float4*)(V + (size_t)(ks + r) * HD_ + c);
            *(float4*)(&sV[r * SVS + c]) = vv;
        }
        __syncthreads();

        // S = Q @ K^T (4x4 per thread)
        float acc[4][4] = {};
#pragma unroll 4
        for (int k = 0; k < HD_; k++) {
            float qr[4], kr[4];
#pragma unroll
            for (int i = 0; i < 4; i++) qr[i] = sQ[(ty * 4 + i) * SQS + k];
#pragma unroll
            for (int j = 0; j < 4; j++) kr[j] = sK[(tx * 4 + j) * SKS + k];
#pragma unroll
            for (int i = 0; i < 4; i++)
#pragma unroll
                for (int j = 0; j < 4; j++)
                    acc[i][j] = fmaf(qr[i], kr[j], acc[i][j]);
        }

        bool diag = (ks == q0);
#pragma unroll
        for (int i = 0; i < 4; i++) {
            int q = q0 + ty * 4 + i;
#pragma unroll
            for (int j = 0; j < 4; j++) {
                float s = acc[i][j] * scale;
                if (diag && (ks + tx * 4 + j) > q) s = -INFINITY;
                acc[i][j] = s;
            }
        }

        // online softmax per row (row spread over 16 lanes)
#pragma unroll
        for (int i = 0; i < 4; i++) {
            float mt = fmaxf(fmaxf(acc[i][0], acc[i][1]), fmaxf(acc[i][2], acc[i][3]));
#pragma unroll
            for (int off = 8; off; off >>= 1)
                mt = fmaxf(mt, __shfl_xor_sync(0xffffffffu, mt, off));
            float mn = fmaxf(m[i], mt);
            float alpha = __expf(m[i] - mn);   // m=-inf first iter -> 0
            float p0 = __expf(acc[i][0] - mn);
            float p1 = __expf(acc[i][1] - mn);
            float p2 = __expf(acc[i][2] - mn);
            float p3 = __expf(acc[i][3] - mn);
            float lt = p0 + p1 + p2 + p3;
#pragma unroll
            for (int off = 8; off; off >>= 1)
                lt += __shfl_xor_sync(0xffffffffu, lt, off);
            l[i] = l[i] * alpha + lt;
            m[i] = mn;
#pragma unroll
            for (int c = 0; c < 8; c++) o[i][c] *= alpha;
            float* pr = sP + (ty * 4 + i) * SPS + tx * 4;
            pr[0] = p0; pr[1] = p1; pr[2] = p2; pr[3] = p3;
        }
        __syncthreads();

        // O += P @ V  (rows ty*4.., cols tx*8..)
#pragma unroll 4
        for (int j = 0; j < FA_BN; j++) {
            float pv[4];
#pragma unroll
            for (int i = 0; i < 4; i++) pv[i] = sP[(ty * 4 + i) * SPS + j];
            float4 v0 = *(float4*)(&sV[j * SVS + tx * 8]);
            float4 v1 = *(float4*)(&sV[j * SVS + tx * 8 + 4]);
#pragma unroll
            for (int i = 0; i < 4; i++) {
                o[i][0] = fmaf(pv[i], v0.x, o[i][0]);
                o[i][1] = fmaf(pv[i], v0.y, o[i][1]);
                o[i][2] = fmaf(pv[i], v0.z, o[i][2]);
                o[i][3] = fmaf(pv[i], v0.w, o[i][3]);
                o[i][4] = fmaf(pv[i], v1.x, o[i][4]);
                o[i][5] = fmaf(pv[i], v1.y, o[i][5]);
                o[i][6] = fmaf(pv[i], v1.z, o[i][6]);
                o[i][7] = fmaf(pv[i], v1.w, o[i][7]);
            }
        }
    }

    // epilogue: normalize, write [B,T,C] layout directly (head h -> cols h*128..)
#pragma unroll
    for (int i = 0; i < 4; i++) {
        float inv = 1.0f / l[i];
        int q = q0 + ty * 4 + i;
        float* dst = g_ao + ((size_t)(b * T_ + q)) * C_ + h * HD_ + tx * 8;
        *(float4*)(dst)     = make_float4(o[i][0]*inv, o[i][1]*inv, o[i][2]*inv, o[i][3]*inv);
        *(float4*)(dst + 4) = make_float4(o[i][4]*inv, o[i][5]*inv, o[i][6]*inv, o[i][7]*inv);
    }
}

// ---------------- launcher --------------------------------------------------
extern "C" void kernel_launch(void* const* d_in, const int* in_sizes, int n_in,
                              void* d_out, int out_size) {
    (void)in_sizes; (void)n_in; (void)out_size;
    const float* x      = (const float*)d_in[0];
    const float* w_qkv  = (const float*)d_in[1];
    const float* w_proj = (const float*)d_in[2];
    const float* q_gain = (const float*)d_in[3];
    float* out = (float*)d_out;

    float *p_xn, *p_qkv, *p_ao;
    cudaGetSymbolAddress((void**)&p_xn, g_xn);
    cudaGetSymbolAddress((void**)&p_qkv, g_qkv);
    cudaGetSymbolAddress((void**)&p_ao, g_ao);

    cudaFuncSetAttribute(k_flash, cudaFuncAttributeMaxDynamicSharedMemorySize, FA_SMEM);

    k_rope<<<T_, 64>>>();
    k_rmsnorm<<<B_ * T_, 256>>>(x);

    dim3 g1(QKVN_ / 128, (B_ * T_) / 128);
    k_sgemm<<<g1, 256>>>(p_xn, w_qkv, p_qkv, B_ * T_, QKVN_, C_);

    int njobs = B_ * T_ * H_ + 2 * B_ * T_ * HKV_;   // warps
    k_qkpost<<<njobs / 8, 256>>>(q_gain);

    dim3 gf(T_ / FA_BM, H_, B_);
    k_flash<<<gf, 256, FA_SMEM>>>();

    dim3 g2(C_ / 128, (B_ * T_) / 128);
    k_sgemm<<<g2, 256>>>(p_ao, w_proj, out, B_ * T_, C_, C_);
}

// round 2
// speedup vs baseline: 1.0274x; 1.0274x over previous
#include <cuda_runtime.h>
#include <math.h>
#include <stdint.h>

#define B_    2
#define T_    2048
#define C_    2048
#define H_    16
#define HKV_  4
#define REP_  4
#define HD_   128
#define KVD_  512
#define QKVN_ 3072          // C + 2*KV_DIM
#define EPS_  1.1920929e-07f

// ---------------- scratch (static device allocations are allowed) ----------
__device__ float g_xn[(size_t)B_ * T_ * C_];       // rmsnorm(x)
__device__ float g_qkv[(size_t)B_ * T_ * QKVN_];   // qkv projection
__device__ float g_q[(size_t)B_ * H_ * T_ * HD_];  // [B,H,T,HD] post norm/rope/gain
__device__ float g_k[(size_t)B_ * HKV_ * T_ * HD_];
__device__ float g_v[(size_t)B_ * HKV_ * T_ * HD_];
__device__ float g_ao[(size_t)B_ * T_ * C_];       // attention out [B,T,C]
__device__ float g_cos[T_ * 64];
__device__ float g_sin[T_ * 64];

// ---------------- RoPE tables (double-precision trig, fast-math immune) ----
__global__ void k_rope() {
    int t = blockIdx.x;
    int j = threadIdx.x;  // 0..63
    float invf = 1.0f / powf(10000.0f, (2.0f * (float)j) / 128.0f);
    float ang  = (float)t * invf;   // matches fp32 outer() in reference
    g_cos[t * 64 + j] = (float)cos((double)ang);
    g_sin[t * 64 + j] = (float)sin((double)ang);
}

// ---------------- input RMSNorm over C=2048, one block per row -------------
__global__ void __launch_bounds__(256) k_rmsnorm(const float* __restrict__ x) {
    int row = blockIdx.x;                        // 0..B*T-1
    const float* xr = x + (size_t)row * C_;
    float ss = 0.f;
    for (int i = threadIdx.x; i < C_; i += 256) {
        float v = xr[i];
        ss = fmaf(v, v, ss);
    }
    __shared__ float sh[8];
    int lane = threadIdx.x & 31, wid = threadIdx.x >> 5;
#pragma unroll
    for (int o = 16; o; o >>= 1) ss += __shfl_xor_sync(0xffffffffu, ss, o);
    if (lane == 0) sh[wid] = ss;
    __syncthreads();
    float tot = (threadIdx.x < 8) ? sh[threadIdx.x] : 0.f;
    if (wid == 0) {
#pragma unroll
        for (int o = 16; o; o >>= 1) tot += __shfl_xor_sync(0xffffffffu, tot, o);
    }
    __shared__ float sb;
    if (threadIdx.x == 0) sb = tot;
    __syncthreads();
    float sc = rsqrtf(sb * (1.0f / C_) + EPS_);
    for (int i = threadIdx.x; i < C_; i += 256)
        g_xn[(size_t)row * C_ + i] = xr[i] * sc;
}

// ---------------- 3xTF32 tensor-core GEMM: C[M,N] = A[M,K] @ B[K,N] --------
// 128x128 block tile, BK=32, 256 threads (8 warps), warp tile 64x32,
// m16n8k8 tf32 mma with hi/lo split (AhBh + AhBl + AlBh) -> ~fp32 accuracy.

__device__ __forceinline__ void split_tf32(float v, uint32_t& h, uint32_t& l) {
    asm("cvt.rna.tf32.f32 %0, %1;" : "=r"(h) : "f"(v));
    float hf = __uint_as_float(h);
    float r = v - hf;
    asm("cvt.rna.tf32.f32 %0, %1;" : "=r"(l) : "f"(r));
}

__device__ __forceinline__ void mma_tf32(float c[4], const uint32_t a[4], const uint32_t b[2]) {
    asm volatile(
        "mma.sync.aligned.m16n8k8.row.col.f32.tf32.tf32.f32 "
        "{%0,%1,%2,%3},{%4,%5,%6,%7},{%8,%9},{%0,%1,%2,%3};"
        : "+f"(c[0]), "+f"(c[1]), "+f"(c[2]), "+f"(c[3])
        : "r"(a[0]), "r"(a[1]), "r"(a[2]), "r"(a[3]), "r"(b[0]), "r"(b[1]));
}

__global__ void __launch_bounds__(256) k_gemm_tf32(const float* __restrict__ A,
                                                   const float* __restrict__ Bm,
                                                   float* __restrict__ Cm,
                                                   int M, int N, int K) {
    __shared__ __align__(16) float As[128][36];   // padded: frag loads conflict-free
    __shared__ __align__(16) float Bs[32][136];

    int tid = threadIdx.x;
    int wid = tid >> 5;
    int lane = tid & 31;
    int gid = lane >> 2;      // 0..7
    int tg  = lane & 3;       // 0..3
    int warp_m = wid >> 2;    // 0..1
    int warp_n = wid & 3;     // 0..3
    int m0 = blockIdx.y * 128, n0 = blockIdx.x * 128;

    float acc[4][4][4] = {};

    for (int k0 = 0; k0 < K; k0 += 32) {
        __syncthreads();
        // A tile 128x32
#pragma unroll
        for (int s = 0; s < 4; s++) {
            int idx = tid + s * 256;          // float4 slot 0..1023
            int r = idx >> 3;
            int c4 = (idx & 7) * 4;
            float4 av = *(const float4*)(A + (size_t)(m0 + r) * K + k0 + c4);
            *(float4*)&As[r][c4] = av;
        }
        // B tile 32x128
#pragma unroll
        for (int s = 0; s < 4; s++) {
            int idx = tid + s * 256;
            int r = idx >> 5;
            int c4 = (idx & 31) * 4;
            float4 bv = *(const float4*)(Bm + (size_t)(k0 + r) * N + n0 + c4);
            *(float4*)&Bs[r][c4] = bv;
        }
        __syncthreads();

#pragma unroll
        for (int ks = 0; ks < 4; ks++) {
            int kk = ks * 8;
            uint32_t ah[4][4], al[4][4];
#pragma unroll
            for (int mt = 0; mt < 4; mt++) {
                int rm = warp_m * 64 + mt * 16 + gid;
                float a0 = As[rm][kk + tg];
                float a1 = As[rm + 8][kk + tg];
                float a2 = As[rm][kk + tg + 4];
                float a3 = As[rm + 8][kk + tg + 4];
                split_tf32(a0, ah[mt][0], al[mt][0]);
                split_tf32(a1, ah[mt][1], al[mt][1]);
                split_tf32(a2, ah[mt][2], al[mt][2]);
                split_tf32(a3, ah[mt][3], al[mt][3]);
            }
            uint32_t bh[4][2], bl[4][2];
#pragma unroll
            for (int nt = 0; nt < 4; nt++) {
                int cn = warp_n * 32 + nt * 8 + gid;
                float b0 = Bs[kk + tg][cn];
                float b1 = Bs[kk + tg + 4][cn];
                split_tf32(b0, bh[nt][0], bl[nt][0]);
                split_tf32(b1, bh[nt][1], bl[nt][1]);
            }
#pragma unroll
            for (int mt = 0; mt < 4; mt++)
#pragma unroll
                for (int nt = 0; nt < 4; nt++) {
                    mma_tf32(acc[mt][nt], ah[mt], bl[nt]);
                    mma_tf32(acc[mt][nt], al[mt], bh[nt]);
                    mma_tf32(acc[mt][nt], ah[mt], bh[nt]);
                }
        }
    }

    // epilogue
#pragma unroll
    for (int mt = 0; mt < 4; mt++) {
#pragma unroll
        for (int nt = 0; nt < 4; nt++) {
            int row = m0 + warp_m * 64 + mt * 16 + gid;
            int col = n0 + warp_n * 32 + nt * 8 + tg * 2;
            *(float2*)(Cm + (size_t)row * N + col) =
                make_float2(acc[mt][nt][0], acc[mt][nt][1]);
            *(float2*)(Cm + (size_t)(row + 8) * N + col) =
                make_float2(acc[mt][nt][2], acc[mt][nt][3]);
        }
    }
}

// ---------------- Q/K rmsnorm + RoPE + gain; V scatter. One warp per row ---
__global__ void __launch_bounds__(256) k_qkpost(const float* __restrict__ qg) {
    int gwarp = (blockIdx.x * 256 + threadIdx.x) >> 5;
    int lane = threadIdx.x & 31;
    const int NQ = B_ * T_ * H_;   // 65536
    const int NK = B_ * T_ * HKV_; // 16384
    if (gwarp < NQ) {
        int h = gwarp % H_;
        int bt = gwarp / H_;
        int t = bt % T_, b = bt / T_;
        const float* src = g_qkv + (size_t)bt * QKVN_ + h * HD_;
        float v0 = src[lane], v1 = src[lane + 32], v2 = src[lane + 64], v3 = src[lane + 96];
        float ss = v0 * v0 + v1 * v1 + v2 * v2 + v3 * v3;
#pragma unroll
        for (int o = 16; o; o >>= 1) ss += __shfl_xor_sync(0xffffffffu, ss, o);
        float sc = rsqrtf(ss * (1.0f / HD_) + EPS_);
        v0 *= sc; v1 *= sc; v2 *= sc; v3 *= sc;
        float c0 = g_cos[t * 64 + lane],      s0 = g_sin[t * 64 + lane];
        float c1 = g_cos[t * 64 + 32 + lane], s1 = g_sin[t * 64 + 32 + lane];
        float r0 = v0 * c0 - v2 * s0;
        float r1 = v1 * c1 - v3 * s1;
        float r2 = v2 * c0 + v0 * s0;
        float r3 = v3 * c1 + v1 * s1;
        float gn = qg[h];
        float* dst = g_q + ((size_t)(b * H_ + h) * T_ + t) * HD_;
        dst[lane] = r0 * gn; dst[lane + 32] = r1 * gn;
        dst[lane + 64] = r2 * gn; dst[lane + 96] = r3 * gn;
    } else if (gwarp < NQ + NK) {
        int w = gwarp - NQ;
        int g = w % HKV_;
        int bt = w / HKV_;
        int t = bt % T_, b = bt / T_;
        const float* src = g_qkv + (size_t)bt * QKVN_ + C_ + g * HD_;
        float v0 = src[lane], v1 = src[lane + 32], v2 = src[lane + 64], v3 = src[lane + 96];
        float ss = v0 * v0 + v1 * v1 + v2 * v2 + v3 * v3;
#pragma unroll
        for (int o = 16; o; o >>= 1) ss += __shfl_xor_sync(0xffffffffu, ss, o);
        float sc = rsqrtf(ss * (1.0f / HD_) + EPS_);
        v0 *= sc; v1 *= sc; v2 *= sc; v3 *= sc;
        float c0 = g_cos[t * 64 + lane],      s0 = g_sin[t * 64 + lane];
        float c1 = g_cos[t * 64 + 32 + lane], s1 = g_sin[t * 64 + 32 + lane];
        float r0 = v0 * c0 - v2 * s0;
        float r1 = v1 * c1 - v3 * s1;
        float r2 = v2 * c0 + v0 * s0;
        float r3 = v3 * c1 + v1 * s1;
        float* dst = g_k + ((size_t)(b * HKV_ + g) * T_ + t) * HD_;
        dst[lane] = r0; dst[lane + 32] = r1; dst[lane + 64] = r2; dst[lane + 96] = r3;
    } else if (gwarp < NQ + 2 * NK) {
        int w = gwarp - NQ - NK;
        int g = w % HKV_;
        int bt = w / HKV_;
        int t = bt % T_, b = bt / T_;
        const float* src = g_qkv + (size_t)bt * QKVN_ + C_ + KVD_ + g * HD_;
        float* dst = g_v + ((size_t)(b * HKV_ + g) * T_ + t) * HD_;
        dst[lane] = src[lane]; dst[lane + 32] = src[lane + 32];
        dst[lane + 64] = src[lane + 64]; dst[lane + 96] = src[lane + 96];
    }
}

// ---------------- causal flash attention, fp32, 64x64 tiles ----------------
#define FA_BM 64
#define FA_BN 64
#define SQS 129
#define SKS 129
#define SVS 132
#define SPS 68
#define FA_SMEM ((FA_BM * SQS + FA_BN * SKS + FA_BN * SVS + FA_BM * SPS) * 4)

__global__ void __launch_bounds__(256) k_flash() {
    extern __shared__ float sm[];
    float* sQ = sm;                       // 64 x 129
    float* sK = sQ + FA_BM * SQS;         // 64 x 129
    float* sV = sK + FA_BN * SKS;         // 64 x 132
    float* sP = sV + FA_BN * SVS;         // 64 x 68

    int tid = threadIdx.x;
    int tx = tid & 15, ty = tid >> 4;     // 16 x 16
    int qt = blockIdx.x;
    int h = blockIdx.y;
    int b = blockIdx.z;
    int g = h >> 2;                       // kv head
    int q0 = qt * FA_BM;

    const float* Q = g_q + ((size_t)(b * H_ + h) * T_ + q0) * HD_;
    const float* K = g_k + (size_t)(b * HKV_ + g) * T_ * HD_;
    const float* V = g_v + (size_t)(b * HKV_ + g) * T_ * HD_;

    // load Q tile (64 x 128)
#pragma unroll
    for (int s = 0; s < 8; s++) {
        int idx = tid + s * 256;          // float4 slot 0..2047
        int r = idx >> 5;
        int c = (idx & 31) * 4;
        float4 qv = *(const float4*)(Q + (size_t)r * HD_ + c);
        sQ[r * SQS + c]     = qv.x;
        sQ[r * SQS + c + 1] = qv.y;
        sQ[r * SQS + c + 2] = qv.z;
        sQ[r * SQS + c + 3] = qv.w;
    }

    float m[4], l[4], o[4][8];
#pragma unroll
    for (int i = 0; i < 4; i++) {
        m[i] = -INFINITY; l[i] = 0.f;
#pragma unroll
        for (int c = 0; c < 8; c++) o[i][c] = 0.f;
    }

    const float scale = 0.08838834764831845f;  // 1/sqrt(128)
    int kend = q0 + FA_BM;

    for (int ks = 0; ks < kend; ks += FA_BN) {
        __syncthreads();   // previous O-update done before overwriting K/V
#pragma unroll
        for (int s = 0; s < 8; s++) {
            int idx = tid + s * 256;
            int r = idx >> 5;
            int c = (idx & 31) * 4;
            float4 kv = *(const float4*)(K + (size_t)(ks + r) * HD_ + c);
            sK[r * SKS + c]     = kv.x;
            sK[r * SKS + c + 1] = kv.y;
            sK[r * SKS + c + 2] = kv.z;
            sK[r * SKS + c + 3] = kv.w;
            float4 vv = *(const float4*)(V + (size_t)(ks + r) * HD_ + c);
            *(float4*)(&sV[r * SVS + c]) = vv;
        }
        __syncthreads();

        // S = Q @ K^T (4x4 per thread)
        float acc[4][4] = {};
#pragma unroll 4
        for (int k = 0; k < HD_; k++) {
            float qr[4], kr[4];
#pragma unroll
            for (int i = 0; i < 4; i++) qr[i] = sQ[(ty * 4 + i) * SQS + k];
#pragma unroll
            for (int j = 0; j < 4; j++) kr[j] = sK[(tx * 4 + j) * SKS + k];
#pragma unroll
            for (int i = 0; i < 4; i++)
#pragma unroll
                for (int j = 0; j < 4; j++)
                    acc[i][j] = fmaf(qr[i], kr[j], acc[i][j]);
        }

        bool diag = (ks == q0);
#pragma unroll
        for (int i = 0; i < 4; i++) {
            int q = q0 + ty * 4 + i;
#pragma unroll
            for (int j = 0; j < 4; j++) {
                float s = acc[i][j] * scale;
                if (diag && (ks + tx * 4 + j) > q) s = -INFINITY;
                acc[i][j] = s;
            }
        }

        // online softmax per row (row spread over 16 lanes)
#pragma unroll
        for (int i = 0; i < 4; i++) {
            float mt = fmaxf(fmaxf(acc[i][0], acc[i][1]), fmaxf(acc[i][2], acc[i][3]));
#pragma unroll
            for (int off = 8; off; off >>= 1)
                mt = fmaxf(mt, __shfl_xor_sync(0xffffffffu, mt, off));
            float mn = fmaxf(m[i], mt);
            float alpha = __expf(m[i] - mn);   // m=-inf first iter -> 0
            float p0 = __expf(acc[i][0] - mn);
            float p1 = __expf(acc[i][1] - mn);
            float p2 = __expf(acc[i][2] - mn);
            float p3 = __expf(acc[i][3] - mn);
            float lt = p0 + p1 + p2 + p3;
#pragma unroll
            for (int off = 8; off; off >>= 1)
                lt += __shfl_xor_sync(0xffffffffu, lt, off);
            l[i] = l[i] * alpha + lt;
            m[i] = mn;
#pragma unroll
            for (int c = 0; c < 8; c++) o[i][c] *= alpha;
            float* pr = sP + (ty * 4 + i) * SPS + tx * 4;
            pr[0] = p0; pr[1] = p1; pr[2] = p2; pr[3] = p3;
        }
        __syncthreads();

        // O += P @ V  (rows ty*4.., cols tx*8..)
#pragma unroll 4
        for (int j = 0; j < FA_BN; j++) {
            float pv[4];
#pragma unroll
            for (int i = 0; i < 4; i++) pv[i] = sP[(ty * 4 + i) * SPS + j];
            float4 v0 = *(float4*)(&sV[j * SVS + tx * 8]);
            float4 v1 = *(float4*)(&sV[j * SVS + tx * 8 + 4]);
#pragma unroll
            for (int i = 0; i < 4; i++) {
                o[i][0] = fmaf(pv[i], v0.x, o[i][0]);
                o[i][1] = fmaf(pv[i], v0.y, o[i][1]);
                o[i][2] = fmaf(pv[i], v0.z, o[i][2]);
                o[i][3] = fmaf(pv[i], v0.w, o[i][3]);
                o[i][4] = fmaf(pv[i], v1.x, o[i][4]);
                o[i][5] = fmaf(pv[i], v1.y, o[i][5]);
                o[i][6] = fmaf(pv[i], v1.z, o[i][6]);
                o[i][7] = fmaf(pv[i], v1.w, o[i][7]);
            }
        }
    }

    // epilogue: normalize, write [B,T,C] layout directly (head h -> cols h*128..)
#pragma unroll
    for (int i = 0; i < 4; i++) {
        float inv = 1.0f / l[i];
        int q = q0 + ty * 4 + i;
        float* dst = g_ao + ((size_t)(b * T_ + q)) * C_ + h * HD_ + tx * 8;
        *(float4*)(dst)     = make_float4(o[i][0]*inv, o[i][1]*inv, o[i][2]*inv, o[i][3]*inv);
        *(float4*)(dst + 4) = make_float4(o[i][4]*inv, o[i][5]*inv, o[i][6]*inv, o[i][7]*inv);
    }
}

// ---------------- launcher --------------------------------------------------
extern "C" void kernel_launch(void* const* d_in, const int* in_sizes, int n_in,
                              void* d_out, int out_size) {
    (void)in_sizes; (void)n_in; (void)out_size;
    const float* x      = (const float*)d_in[0];
    const float* w_qkv  = (const float*)d_in[1];
    const float* w_proj = (const float*)d_in[2];
    const float* q_gain = (const float*)d_in[3];
    float* out = (float*)d_out;

    float *p_xn, *p_qkv, *p_ao;
    cudaGetSymbolAddress((void**)&p_xn, g_xn);
    cudaGetSymbolAddress((void**)&p_qkv, g_qkv);
    cudaGetSymbolAddress((void**)&p_ao, g_ao);

    cudaFuncSetAttribute(k_flash, cudaFuncAttributeMaxDynamicSharedMemorySize, FA_SMEM);

    k_rope<<<T_, 64>>>();
    k_rmsnorm<<<B_ * T_, 256>>>(x);

    dim3 g1(QKVN_ / 128, (B_ * T_) / 128);
    k_gemm_tf32<<<g1, 256>>>(p_xn, w_qkv, p_qkv, B_ * T_, QKVN_, C_);

    int njobs = B_ * T_ * H_ + 2 * B_ * T_ * HKV_;   // warps
    k_qkpost<<<njobs / 8, 256>>>(q_gain);

    dim3 gf(T_ / FA_BM, H_, B_);
    k_flash<<<gf, 256, FA_SMEM>>>();

    dim3 g2(C_ / 128, (B_ * T_) / 128);
    k_gemm_tf32<<<g2, 256>>>(p_ao, w_proj, out, B_ * T_, C_, C_);
}

// round 4
// speedup vs baseline: 1.5735x; 1.5315x over previous
#include <cuda_runtime.h>
#include <cuda_bf16.h>
#include <math.h>
#include <stdint.h>

#define B_    2
#define T_    2048
#define C_    2048
#define H_    16
#define HKV_  4
#define HD_   128
#define KVD_  512
#define QKVN_ 3072
#define EPS_  1.1920929e-07f
#define M_ROWS (B_ * T_)     // 4096

// ---------------- scratch ----------------------------------------------------
__device__ __nv_bfloat16 g_ah[(size_t)M_ROWS * C_];   // A hi (rmsnorm(x), later attn out)
__device__ __nv_bfloat16 g_al[(size_t)M_ROWS * C_];   // A lo
__device__ __nv_bfloat16 g_bh1[(size_t)QKVN_ * C_];   // w_qkv^T hi  [N,K]
__device__ __nv_bfloat16 g_bl1[(size_t)QKVN_ * C_];
__device__ __nv_bfloat16 g_bh2[(size_t)C_ * C_];      // w_proj^T hi [N,K]
__device__ __nv_bfloat16 g_bl2[(size_t)C_ * C_];
__device__ float g_qkv[(size_t)M_ROWS * QKVN_];
__device__ float g_q[(size_t)B_ * H_ * T_ * HD_];
__device__ float g_k[(size_t)B_ * HKV_ * T_ * HD_];
__device__ float g_v[(size_t)B_ * HKV_ * T_ * HD_];
__device__ float g_cos[T_ * 64];
__device__ float g_sin[T_ * 64];

// ---------------- PTX helpers (portable sm_80+ subset only) -------------------
__device__ __forceinline__ uint32_t smem_u32(const void* p) {
    uint32_t a;
    asm("{ .reg .u64 t; cvta.to.shared.u64 t, %1; cvt.u32.u64 %0, t; }" : "=r"(a) : "l"(p));
    return a;
}
__device__ __forceinline__ void cpa16(uint32_t dst, const void* src) {
    asm volatile("cp.async.cg.shared.global [%0], [%1], 16;" :: "r"(dst), "l"(src) : "memory");
}
__device__ __forceinline__ void cpa_commit() { asm volatile("cp.async.commit_group;" ::: "memory"); }
__device__ __forceinline__ void cpa_wait0()  { asm volatile("cp.async.wait_group 0;" ::: "memory"); }
__device__ __forceinline__ void cpa_wait1()  { asm volatile("cp.async.wait_group 1;" ::: "memory"); }

__device__ __forceinline__ void ldm_x4(uint32_t* r, uint32_t addr) {
    asm volatile("ldmatrix.sync.aligned.m8n8.x4.shared.b16 {%0,%1,%2,%3}, [%4];"
                 : "=r"(r[0]), "=r"(r[1]), "=r"(r[2]), "=r"(r[3]) : "r"(addr));
}
__device__ __forceinline__ void mma_bf16(float* c, const uint32_t* a, const uint32_t* b) {
    asm volatile(
        "mma.sync.aligned.m16n8k16.row.col.f32.bf16.bf16.f32 "
        "{%0,%1,%2,%3},{%4,%5,%6,%7},{%8,%9},{%0,%1,%2,%3};"
        : "+f"(c[0]), "+f"(c[1]), "+f"(c[2]), "+f"(c[3])
        : "r"(a[0]), "r"(a[1]), "r"(a[2]), "r"(a[3]), "r"(b[0]), "r"(b[1]));
}

// ---------------- RoPE tables -------------------------------------------------
__global__ void k_rope() {
    int t = blockIdx.x;
    int j = threadIdx.x;
    float invf = 1.0f / powf(10000.0f, (2.0f * (float)j) / 128.0f);
    float ang = (float)t * invf;
    g_cos[t * 64 + j] = (float)cos((double)ang);
    g_sin[t * 64 + j] = (float)sin((double)ang);
}

// ---------------- input RMSNorm -> bf16 hi/lo split ----------------------------
__global__ void __launch_bounds__(256) k_rmsnorm(const float* __restrict__ x) {
    int row = blockIdx.x;
    const float* xr = x + (size_t)row * C_;
    float ss = 0.f;
    for (int i = threadIdx.x; i < C_; i += 256) { float v = xr[i]; ss = fmaf(v, v, ss); }
    __shared__ float sh[8];
    int lane = threadIdx.x & 31, wid = threadIdx.x >> 5;
#pragma unroll
    for (int o = 16; o; o >>= 1) ss += __shfl_xor_sync(0xffffffffu, ss, o);
    if (lane == 0) sh[wid] = ss;
    __syncthreads();
    float tot = (threadIdx.x < 8) ? sh[threadIdx.x] : 0.f;
    if (wid == 0) {
#pragma unroll
        for (int o = 16; o; o >>= 1) tot += __shfl_xor_sync(0xffffffffu, tot, o);
    }
    __shared__ float sb;
    if (threadIdx.x == 0) sb = tot;
    __syncthreads();
    float sc = rsqrtf(sb * (1.0f / C_) + EPS_);
    for (int i = threadIdx.x; i < C_; i += 256) {
        float v = xr[i] * sc;
        __nv_bfloat16 h = __float2bfloat16(v);
        g_ah[(size_t)row * C_ + i] = h;
        g_al[(size_t)row * C_ + i] = __float2bfloat16(v - __bfloat162float(h));
    }
}

// ---------------- W[K,N] -> W^T[N,K] bf16 hi/lo split ---------------------------
__global__ void __launch_bounds__(256) k_splitw(const float* __restrict__ W,
                                                __nv_bfloat16* __restrict__ Bh,
                                                __nv_bfloat16* __restrict__ Bl,
                                                int K, int N) {
    __shared__ float ts[32][33];
    int nb = blockIdx.x * 32, kb = blockIdx.y * 32;
    int tx = threadIdx.x & 31, ty = threadIdx.x >> 5;
#pragma unroll
    for (int r = ty; r < 32; r += 8)
        ts[r][tx] = W[(size_t)(kb + r) * N + nb + tx];
    __syncthreads();
#pragma unroll
    for (int r = ty; r < 32; r += 8) {
        float v = ts[tx][r];            // = W[kb+tx][nb+r]
        __nv_bfloat16 h = __float2bfloat16(v);
        size_t o = (size_t)(nb + r) * K + kb + tx;
        Bh[o] = h;
        Bl[o] = __float2bfloat16(v - __bfloat162float(h));
    }
}

// ---------------- bf16-split mma.sync GEMM: C[M,N]=A[M,K]@B^T -------------------
// 128x128 block tile, BK=32, 256 threads (8 warps), warp tile 64x32.
// smem tiles row-padded to 80B (stride/16 odd -> ldmatrix conflict-free).
#define TSTRIDE 80
#define TILE_BYTES (128 * TSTRIDE)          // 10240
#define STAGE_BYTES (4 * TILE_BYTES)        // Ah, Al, Bh, Bl
#define GSMEM (2 * STAGE_BYTES)             // 81920

__global__ void __launch_bounds__(256) k_gemm_bf16(const __nv_bfloat16* __restrict__ Ah,
                                                   const __nv_bfloat16* __restrict__ Al,
                                                   const __nv_bfloat16* __restrict__ Bh,
                                                   const __nv_bfloat16* __restrict__ Bl,
                                                   float* __restrict__ Cm,
                                                   int M, int N, int K) {
    extern __shared__ char smraw[];
    uint32_t sb = smem_u32(smraw);

    int tid = threadIdx.x;
    int wid = tid >> 5, lane = tid & 31;
    int warp_m = wid >> 2, warp_n = wid & 3;
    int m0 = blockIdx.y * 128, n0 = blockIdx.x * 128;
    int NIT = K >> 5;

    const __nv_bfloat16* bases[4] = {
        Ah + (size_t)m0 * K, Al + (size_t)m0 * K,
        Bh + (size_t)n0 * K, Bl + (size_t)n0 * K };

    // stage loader: 4 tiles x (128 rows x 32 bf16) = 2048 x 16B chunks / 256 thr
    auto load_stage = [&](int it, int buf) {
        int k0 = it << 5;
        uint32_t dst0 = sb + buf * STAGE_BYTES;
#pragma unroll
        for (int s = 0; s < 8; s++) {
            int c = tid + s * 256;
            int t = c >> 9;
            int cw = c & 511;
            int row = cw >> 2, q = cw & 3;
            const __nv_bfloat16* src = bases[t] + (size_t)row * K + k0 + q * 8;
            cpa16(dst0 + t * TILE_BYTES + row * TSTRIDE + q * 16, src);
        }
    };

    float acc[4][4][4] = {};

    // fragment address offsets (constant per thread)
    uint32_t a_off = (uint32_t)(warp_m * 64 + (lane & 15)) * TSTRIDE + ((lane >> 4) << 4);
    uint32_t b_off = (uint32_t)(warp_n * 32 + (lane & 7) + ((lane & 16) >> 1)) * TSTRIDE
                   + ((lane & 8) << 1);

    load_stage(0, 0);
    cpa_commit();

    for (int it = 0; it < NIT; it++) {
        int buf = it & 1;
        if (it + 1 < NIT) {
            load_stage(it + 1, buf ^ 1);
            cpa_commit();
            cpa_wait1();
        } else {
            cpa_wait0();
        }
        __syncthreads();

        uint32_t stg = sb + buf * STAGE_BYTES;
        uint32_t aH = stg + a_off;
        uint32_t aL = stg + TILE_BYTES + a_off;
        uint32_t bH = stg + 2 * TILE_BYTES + b_off;
        uint32_t bL = stg + 3 * TILE_BYTES + b_off;

#pragma unroll
        for (int ks = 0; ks < 2; ks++) {
            uint32_t ko = ks * 32;          // 16 bf16 = 32B per k-halfstep
            uint32_t ah[4][4], al[4][4], bh[4][2], bl[4][2];
#pragma unroll
            for (int mt = 0; mt < 4; mt++) {
                ldm_x4(ah[mt], aH + ko + mt * 16 * TSTRIDE);
                ldm_x4(al[mt], aL + ko + mt * 16 * TSTRIDE);
            }
#pragma unroll
            for (int bp = 0; bp < 2; bp++) {
                uint32_t r[4];
                ldm_x4(r, bH + ko + bp * 16 * TSTRIDE);
                bh[2 * bp][0] = r[0]; bh[2 * bp][1] = r[1];
                bh[2 * bp + 1][0] = r[2]; bh[2 * bp + 1][1] = r[3];
                ldm_x4(r, bL + ko + bp * 16 * TSTRIDE);
                bl[2 * bp][0] = r[0]; bl[2 * bp][1] = r[1];
                bl[2 * bp + 1][0] = r[2]; bl[2 * bp + 1][1] = r[3];
            }
#pragma unroll
            for (int mt = 0; mt < 4; mt++)
#pragma unroll
                for (int nt = 0; nt < 4; nt++) {
                    mma_bf16(acc[mt][nt], ah[mt], bh[nt]);
                    mma_bf16(acc[mt][nt], ah[mt], bl[nt]);
                    mma_bf16(acc[mt][nt], al[mt], bh[nt]);
                }
        }
        __syncthreads();
    }

    // epilogue: d0=(r,c) d1=(r,c+1) d2=(r+8,c) d3=(r+8,c+1); r=t/4, c=2*(t%4)
    int gid = lane >> 2, tg = lane & 3;
#pragma unroll
    for (int mt = 0; mt < 4; mt++) {
#pragma unroll
        for (int nt = 0; nt < 4; nt++) {
            int row = m0 + warp_m * 64 + mt * 16 + gid;
            int col = n0 + warp_n * 32 + nt * 8 + tg * 2;
            *(float2*)(Cm + (size_t)row * N + col) =
                make_float2(acc[mt][nt][0], acc[mt][nt][1]);
            *(float2*)(Cm + (size_t)(row + 8) * N + col) =
                make_float2(acc[mt][nt][2], acc[mt][nt][3]);
        }
    }
}

// ---------------- Q/K rmsnorm + RoPE + gain; V scatter --------------------------
__global__ void __launch_bounds__(256) k_qkpost(const float* __restrict__ qg) {
    int gwarp = (blockIdx.x * 256 + threadIdx.x) >> 5;
    int lane = threadIdx.x & 31;
    const int NQ = B_ * T_ * H_;
    const int NK = B_ * T_ * HKV_;
    if (gwarp < NQ) {
        int h = gwarp % H_;
        int bt = gwarp / H_;
        int t = bt % T_, b = bt / T_;
        const float* src = g_qkv + (size_t)bt * QKVN_ + h * HD_;
        float v0 = src[lane], v1 = src[lane + 32], v2 = src[lane + 64], v3 = src[lane + 96];
        float ss = v0 * v0 + v1 * v1 + v2 * v2 + v3 * v3;
#pragma unroll
        for (int o = 16; o; o >>= 1) ss += __shfl_xor_sync(0xffffffffu, ss, o);
        float sc = rsqrtf(ss * (1.0f / HD_) + EPS_);
        v0 *= sc; v1 *= sc; v2 *= sc; v3 *= sc;
        float c0 = g_cos[t * 64 + lane],      s0 = g_sin[t * 64 + lane];
        float c1 = g_cos[t * 64 + 32 + lane], s1 = g_sin[t * 64 + 32 + lane];
        float gn = qg[h];
        float* dst = g_q + ((size_t)(b * H_ + h) * T_ + t) * HD_;
        dst[lane]      = (v0 * c0 - v2 * s0) * gn;
        dst[lane + 32] = (v1 * c1 - v3 * s1) * gn;
        dst[lane + 64] = (v2 * c0 + v0 * s0) * gn;
        dst[lane + 96] = (v3 * c1 + v1 * s1) * gn;
    } else if (gwarp < NQ + NK) {
        int w = gwarp - NQ;
        int g = w % HKV_;
        int bt = w / HKV_;
        int t = bt % T_, b = bt / T_;
        const float* src = g_qkv + (size_t)bt * QKVN_ + C_ + g * HD_;
        float v0 = src[lane], v1 = src[lane + 32], v2 = src[lane + 64], v3 = src[lane + 96];
        float ss = v0 * v0 + v1 * v1 + v2 * v2 + v3 * v3;
#pragma unroll
        for (int o = 16; o; o >>= 1) ss += __shfl_xor_sync(0xffffffffu, ss, o);
        float sc = rsqrtf(ss * (1.0f / HD_) + EPS_);
        v0 *= sc; v1 *= sc; v2 *= sc; v3 *= sc;
        float c0 = g_cos[t * 64 + lane],      s0 = g_sin[t * 64 + lane];
        float c1 = g_cos[t * 64 + 32 + lane], s1 = g_sin[t * 64 + 32 + lane];
        float* dst = g_k + ((size_t)(b * HKV_ + g) * T_ + t) * HD_;
        dst[lane]      = v0 * c0 - v2 * s0;
        dst[lane + 32] = v1 * c1 - v3 * s1;
        dst[lane + 64] = v2 * c0 + v0 * s0;
        dst[lane + 96] = v3 * c1 + v1 * s1;
    } else if (gwarp < NQ + 2 * NK) {
        int w = gwarp - NQ - NK;
        int g = w % HKV_;
        int bt = w / HKV_;
        int t = bt % T_, b = bt / T_;
        const float* src = g_qkv + (size_t)bt * QKVN_ + C_ + KVD_ + g * HD_;
        float* dst = g_v + ((size_t)(b * HKV_ + g) * T_ + t) * HD_;
        dst[lane] = src[lane]; dst[lane + 32] = src[lane + 32];
        dst[lane + 64] = src[lane + 64]; dst[lane + 96] = src[lane + 96];
    }
}

// ---------------- causal flash attention, fp32, 64x64 tiles ---------------------
#define FA_BM 64
#define FA_BN 64
#define SQS 129
#define SKS 129
#define SVS 132
#define SPS 68
#define FA_SMEM ((FA_BM * SQS + FA_BN * SKS + FA_BN * SVS + FA_BM * SPS) * 4)

__global__ void __launch_bounds__(256) k_flash() {
    extern __shared__ float sm[];
    float* sQ = sm;
    float* sK = sQ + FA_BM * SQS;
    float* sV = sK + FA_BN * SKS;
    float* sP = sV + FA_BN * SVS;

    int tid = threadIdx.x;
    int tx = tid & 15, ty = tid >> 4;
    int qt = blockIdx.x;
    int h = blockIdx.y;
    int b = blockIdx.z;
    int g = h >> 2;
    int q0 = qt * FA_BM;

    const float* Q = g_q + ((size_t)(b * H_ + h) * T_ + q0) * HD_;
    const float* K = g_k + (size_t)(b * HKV_ + g) * T_ * HD_;
    const float* V = g_v + (size_t)(b * HKV_ + g) * T_ * HD_;

#pragma unroll
    for (int s = 0; s < 8; s++) {
        int idx = tid + s * 256;
        int r = idx >> 5;
        int c = (idx & 31) * 4;
        float4 qv = *(const float4*)(Q + (size_t)r * HD_ + c);
        sQ[r * SQS + c] = qv.x; sQ[r * SQS + c + 1] = qv.y;
        sQ[r * SQS + c + 2] = qv.z; sQ[r * SQS + c + 3] = qv.w;
    }

    float m[4], l[4], o[4][8];
#pragma unroll
    for (int i = 0; i < 4; i++) {
        m[i] = -INFINITY; l[i] = 0.f;
#pragma unroll
        for (int c = 0; c < 8; c++) o[i][c] = 0.f;
    }

    const float scale = 0.08838834764831845f;
    int kend = q0 + FA_BM;

    for (int ks = 0; ks < kend; ks += FA_BN) {
        __syncthreads();
#pragma unroll
        for (int s = 0; s < 8; s++) {
            int idx = tid + s * 256;
            int r = idx >> 5;
            int c = (idx & 31) * 4;
            float4 kv = *(const float4*)(K + (size_t)(ks + r) * HD_ + c);
            sK[r * SKS + c] = kv.x; sK[r * SKS + c + 1] = kv.y;
            sK[r * SKS + c + 2] = kv.z; sK[r * SKS + c + 3] = kv.w;
            float4 vv = *(const float4*)(V + (size_t)(ks + r) * HD_ + c);
            *(float4*)(&sV[r * SVS + c]) = vv;
        }
        __syncthreads();

        float acc[4][4] = {};
#pragma unroll 4
        for (int k = 0; k < HD_; k++) {
            float qr[4], kr[4];
#pragma unroll
            for (int i = 0; i < 4; i++) qr[i] = sQ[(ty * 4 + i) * SQS + k];
#pragma unroll
            for (int j = 0; j < 4; j++) kr[j] = sK[(tx * 4 + j) * SKS + k];
#pragma unroll
            for (int i = 0; i < 4; i++)
#pragma unroll
                for (int j = 0; j < 4; j++)
                    acc[i][j] = fmaf(qr[i], kr[j], acc[i][j]);
        }

        bool diag = (ks == q0);
#pragma unroll
        for (int i = 0; i < 4; i++) {
            int q = q0 + ty * 4 + i;
#pragma unroll
            for (int j = 0; j < 4; j++) {
                float s = acc[i][j] * scale;
                if (diag && (ks + tx * 4 + j) > q) s = -INFINITY;
                acc[i][j] = s;
            }
        }

#pragma unroll
        for (int i = 0; i < 4; i++) {
            float mt = fmaxf(fmaxf(acc[i][0], acc[i][1]), fmaxf(acc[i][2], acc[i][3]));
#pragma unroll
            for (int off = 8; off; off >>= 1)
                mt = fmaxf(mt, __shfl_xor_sync(0xffffffffu, mt, off));
            float mn = fmaxf(m[i], mt);
            float alpha = __expf(m[i] - mn);
            float p0 = __expf(acc[i][0] - mn);
            float p1 = __expf(acc[i][1] - mn);
            float p2 = __expf(acc[i][2] - mn);
            float p3 = __expf(acc[i][3] - mn);
            float lt = p0 + p1 + p2 + p3;
#pragma unroll
            for (int off = 8; off; off >>= 1)
                lt += __shfl_xor_sync(0xffffffffu, lt, off);
            l[i] = l[i] * alpha + lt;
            m[i] = mn;
#pragma unroll
            for (int c = 0; c < 8; c++) o[i][c] *= alpha;
            float* pr = sP + (ty * 4 + i) * SPS + tx * 4;
            pr[0] = p0; pr[1] = p1; pr[2] = p2; pr[3] = p3;
        }
        __syncthreads();

#pragma unroll 4
        for (int j = 0; j < FA_BN; j++) {
            float pv[4];
#pragma unroll
            for (int i = 0; i < 4; i++) pv[i] = sP[(ty * 4 + i) * SPS + j];
            float4 v0 = *(float4*)(&sV[j * SVS + tx * 8]);
            float4 v1 = *(float4*)(&sV[j * SVS + tx * 8 + 4]);
#pragma unroll
            for (int i = 0; i < 4; i++) {
                o[i][0] = fmaf(pv[i], v0.x, o[i][0]);
                o[i][1] = fmaf(pv[i], v0.y, o[i][1]);
                o[i][2] = fmaf(pv[i], v0.z, o[i][2]);
                o[i][3] = fmaf(pv[i], v0.w, o[i][3]);
                o[i][4] = fmaf(pv[i], v1.x, o[i][4]);
                o[i][5] = fmaf(pv[i], v1.y, o[i][5]);
                o[i][6] = fmaf(pv[i], v1.z, o[i][6]);
                o[i][7] = fmaf(pv[i], v1.w, o[i][7]);
            }
        }
    }

    // epilogue: normalize and write bf16 hi/lo split of attention output
#pragma unroll
    for (int i = 0; i < 4; i++) {
        float inv = 1.0f / l[i];
        int q = q0 + ty * 4 + i;
        size_t base = ((size_t)(b * T_ + q)) * C_ + h * HD_ + tx * 8;
        __align__(16) __nv_bfloat16 hi[8], lo[8];
#pragma unroll
        for (int c = 0; c < 8; c++) {
            float v = o[i][c] * inv;
            hi[c] = __float2bfloat16(v);
            lo[c] = __float2bfloat16(v - __bfloat162float(hi[c]));
        }
        *(uint4*)(g_ah + base) = *(uint4*)hi;
        *(uint4*)(g_al + base) = *(uint4*)lo;
    }
}

// ---------------- launcher -------------------------------------------------------
extern "C" void kernel_launch(void* const* d_in, const int* in_sizes, int n_in,
                              void* d_out, int out_size) {
    (void)in_sizes; (void)n_in; (void)out_size;
    const float* x      = (const float*)d_in[0];
    const float* w_qkv  = (const float*)d_in[1];
    const float* w_proj = (const float*)d_in[2];
    const float* q_gain = (const float*)d_in[3];
    float* out = (float*)d_out;

    __nv_bfloat16 *p_ah, *p_al, *p_bh1, *p_bl1, *p_bh2, *p_bl2;
    float* p_qkv;
    cudaGetSymbolAddress((void**)&p_ah, g_ah);
    cudaGetSymbolAddress((void**)&p_al, g_al);
    cudaGetSymbolAddress((void**)&p_bh1, g_bh1);
    cudaGetSymbolAddress((void**)&p_bl1, g_bl1);
    cudaGetSymbolAddress((void**)&p_bh2, g_bh2);
    cudaGetSymbolAddress((void**)&p_bl2, g_bl2);
    cudaGetSymbolAddress((void**)&p_qkv, g_qkv);

    cudaFuncSetAttribute(k_flash, cudaFuncAttributeMaxDynamicSharedMemorySize, FA_SMEM);
    cudaFuncSetAttribute(k_gemm_bf16, cudaFuncAttributeMaxDynamicSharedMemorySize, GSMEM);

    k_rope<<<T_, 64>>>();
    k_rmsnorm<<<M_ROWS, 256>>>(x);

    dim3 gw1(QKVN_ / 32, C_ / 32);
    k_splitw<<<gw1, 256>>>(w_qkv, p_bh1, p_bl1, C_, QKVN_);
    dim3 gw2(C_ / 32, C_ / 32);
    k_splitw<<<gw2, 256>>>(w_proj, p_bh2, p_bl2, C_, C_);

    dim3 g1(QKVN_ / 128, M_ROWS / 128);
    k_gemm_bf16<<<g1, 256, GSMEM>>>(p_ah, p_al, p_bh1, p_bl1, p_qkv, M_ROWS, QKVN_, C_);

    int njobs = B_ * T_ * H_ + 2 * B_ * T_ * HKV_;
    k_qkpost<<<njobs / 8, 256>>>(q_gain);

    dim3 gf(T_ / FA_BM, H_, B_);
    k_flash<<<gf, 256, FA_SMEM>>>();

    dim3 g2(C_ / 128, M_ROWS / 128);
    k_gemm_bf16<<<g2, 256, GSMEM>>>(p_ah, p_al, p_bh2, p_bl2, out, M_ROWS, C_, C_);
}

// round 5
// speedup vs baseline: 3.0076x; 1.9114x over previous
#include <cuda_runtime.h>
#include <cuda_bf16.h>
#include <math.h>
#include <stdint.h>

#define B_    2
#define T_    2048
#define C_    2048
#define H_    16
#define HKV_  4
#define HD_   128
#define KVD_  512
#define QKVN_ 3072
#define EPS_  1.1920929e-07f
#define M_ROWS (B_ * T_)     // 4096
#define SCALE_ 0.08838834764831845f

// ---------------- scratch -----------------------------------------------------
__device__ __nv_bfloat16 g_ah[(size_t)M_ROWS * C_];   // A hi (rmsnorm(x), later attn out)
__device__ __nv_bfloat16 g_al[(size_t)M_ROWS * C_];   // A lo
__device__ __nv_bfloat16 g_bh1[(size_t)QKVN_ * C_];   // w_qkv^T hi  [N,K]
__device__ __nv_bfloat16 g_bl1[(size_t)QKVN_ * C_];
__device__ __nv_bfloat16 g_bh2[(size_t)C_ * C_];      // w_proj^T hi [N,K]
__device__ __nv_bfloat16 g_bl2[(size_t)C_ * C_];
__device__ float g_qkv[(size_t)M_ROWS * QKVN_];
__device__ __nv_bfloat16 g_qh[(size_t)B_ * H_ * T_ * HD_];
__device__ __nv_bfloat16 g_ql[(size_t)B_ * H_ * T_ * HD_];
__device__ __nv_bfloat16 g_kh[(size_t)B_ * HKV_ * T_ * HD_];
__device__ __nv_bfloat16 g_kl[(size_t)B_ * HKV_ * T_ * HD_];
__device__ __nv_bfloat16 g_vth[(size_t)B_ * HKV_ * HD_ * T_];  // [b,g][hd][t]
__device__ __nv_bfloat16 g_vtl[(size_t)B_ * HKV_ * HD_ * T_];
__device__ float g_cos[T_ * 64];
__device__ float g_sin[T_ * 64];

// ---------------- PTX helpers ---------------------------------------------------
__device__ __forceinline__ uint32_t smem_u32(const void* p) {
    uint32_t a;
    asm("{ .reg .u64 t; cvta.to.shared.u64 t, %1; cvt.u32.u64 %0, t; }" : "=r"(a) : "l"(p));
    return a;
}
__device__ __forceinline__ void cpa16(uint32_t dst, const void* src) {
    asm volatile("cp.async.cg.shared.global [%0], [%1], 16;" :: "r"(dst), "l"(src) : "memory");
}
__device__ __forceinline__ void cpa_commit() { asm volatile("cp.async.commit_group;" ::: "memory"); }
__device__ __forceinline__ void cpa_wait0()  { asm volatile("cp.async.wait_group 0;" ::: "memory"); }
__device__ __forceinline__ void cpa_wait1()  { asm volatile("cp.async.wait_group 1;" ::: "memory"); }

__device__ __forceinline__ void ldm_x4(uint32_t* r, uint32_t addr) {
    asm volatile("ldmatrix.sync.aligned.m8n8.x4.shared.b16 {%0,%1,%2,%3}, [%4];"
                 : "=r"(r[0]), "=r"(r[1]), "=r"(r[2]), "=r"(r[3]) : "r"(addr));
}
__device__ __forceinline__ void mma_bf16(float* c, const uint32_t* a, const uint32_t* b) {
    asm volatile(
        "mma.sync.aligned.m16n8k16.row.col.f32.bf16.bf16.f32 "
        "{%0,%1,%2,%3},{%4,%5,%6,%7},{%8,%9},{%0,%1,%2,%3};"
        : "+f"(c[0]), "+f"(c[1]), "+f"(c[2]), "+f"(c[3])
        : "r"(a[0]), "r"(a[1]), "r"(a[2]), "r"(a[3]), "r"(b[0]), "r"(b[1]));
}
__device__ __forceinline__ void bsplit(float v, __nv_bfloat16& h, __nv_bfloat16& l) {
    h = __float2bfloat16(v);
    l = __float2bfloat16(v - __bfloat162float(h));
}

// ---------------- RoPE tables ---------------------------------------------------
__global__ void k_rope() {
    int t = blockIdx.x;
    int j = threadIdx.x;
    float invf = 1.0f / powf(10000.0f, (2.0f * (float)j) / 128.0f);
    float ang = (float)t * invf;
    g_cos[t * 64 + j] = (float)cos((double)ang);
    g_sin[t * 64 + j] = (float)sin((double)ang);
}

// ---------------- input RMSNorm -> bf16 hi/lo split -------------------------------
__global__ void __launch_bounds__(256) k_rmsnorm(const float* __restrict__ x) {
    int row = blockIdx.x;
    const float* xr = x + (size_t)row * C_;
    float ss = 0.f;
    for (int i = threadIdx.x; i < C_; i += 256) { float v = xr[i]; ss = fmaf(v, v, ss); }
    __shared__ float sh[8];
    int lane = threadIdx.x & 31, wid = threadIdx.x >> 5;
#pragma unroll
    for (int o = 16; o; o >>= 1) ss += __shfl_xor_sync(0xffffffffu, ss, o);
    if (lane == 0) sh[wid] = ss;
    __syncthreads();
    float tot = (threadIdx.x < 8) ? sh[threadIdx.x] : 0.f;
    if (wid == 0) {
#pragma unroll
        for (int o = 16; o; o >>= 1) tot += __shfl_xor_sync(0xffffffffu, tot, o);
    }
    __shared__ float sb;
    if (threadIdx.x == 0) sb = tot;
    __syncthreads();
    float sc = rsqrtf(sb * (1.0f / C_) + EPS_);
    for (int i = threadIdx.x; i < C_; i += 256) {
        float v = xr[i] * sc;
        __nv_bfloat16 h, l;
        bsplit(v, h, l);
        g_ah[(size_t)row * C_ + i] = h;
        g_al[(size_t)row * C_ + i] = l;
    }
}

// ---------------- W[K,N] -> W^T[N,K] bf16 hi/lo split -----------------------------
__global__ void __launch_bounds__(256) k_splitw(const float* __restrict__ W,
                                                __nv_bfloat16* __restrict__ Bh,
                                                __nv_bfloat16* __restrict__ Bl,
                                                int K, int N) {
    __shared__ float ts[32][33];
    int nb = blockIdx.x * 32, kb = blockIdx.y * 32;
    int tx = threadIdx.x & 31, ty = threadIdx.x >> 5;
#pragma unroll
    for (int r = ty; r < 32; r += 8)
        ts[r][tx] = W[(size_t)(kb + r) * N + nb + tx];
    __syncthreads();
#pragma unroll
    for (int r = ty; r < 32; r += 8) {
        float v = ts[tx][r];
        __nv_bfloat16 h, l;
        bsplit(v, h, l);
        size_t o = (size_t)(nb + r) * K + kb + tx;
        Bh[o] = h;
        Bl[o] = l;
    }
}

// ---------------- bf16-split mma.sync GEMM (unchanged, validated R4) ---------------
#define TSTRIDE 80
#define TILE_BYTES (128 * TSTRIDE)
#define STAGE_BYTES (4 * TILE_BYTES)
#define GSMEM (2 * STAGE_BYTES)

__global__ void __launch_bounds__(256) k_gemm_bf16(const __nv_bfloat16* __restrict__ Ah,
                                                   const __nv_bfloat16* __restrict__ Al,
                                                   const __nv_bfloat16* __restrict__ Bh,
                                                   const __nv_bfloat16* __restrict__ Bl,
                                                   float* __restrict__ Cm,
                                                   int M, int N, int K) {
    extern __shared__ char smraw[];
    uint32_t sb = smem_u32(smraw);

    int tid = threadIdx.x;
    int wid = tid >> 5, lane = tid & 31;
    int warp_m = wid >> 2, warp_n = wid & 3;
    int m0 = blockIdx.y * 128, n0 = blockIdx.x * 128;
    int NIT = K >> 5;

    const __nv_bfloat16* bases[4] = {
        Ah + (size_t)m0 * K, Al + (size_t)m0 * K,
        Bh + (size_t)n0 * K, Bl + (size_t)n0 * K };

    auto load_stage = [&](int it, int buf) {
        int k0 = it << 5;
        uint32_t dst0 = sb + buf * STAGE_BYTES;
#pragma unroll
        for (int s = 0; s < 8; s++) {
            int c = tid + s * 256;
            int t = c >> 9;
            int cw = c & 511;
            int row = cw >> 2, q = cw & 3;
            const __nv_bfloat16* src = bases[t] + (size_t)row * K + k0 + q * 8;
            cpa16(dst0 + t * TILE_BYTES + row * TSTRIDE + q * 16, src);
        }
    };

    float acc[4][4][4] = {};
    uint32_t a_off = (uint32_t)(warp_m * 64 + (lane & 15)) * TSTRIDE + ((lane >> 4) << 4);
    uint32_t b_off = (uint32_t)(warp_n * 32 + (lane & 7) + ((lane & 16) >> 1)) * TSTRIDE
                   + ((lane & 8) << 1);

    load_stage(0, 0);
    cpa_commit();

    for (int it = 0; it < NIT; it++) {
        int buf = it & 1;
        if (it + 1 < NIT) {
            load_stage(it + 1, buf ^ 1);
            cpa_commit();
            cpa_wait1();
        } else {
            cpa_wait0();
        }
        __syncthreads();

        uint32_t stg = sb + buf * STAGE_BYTES;
        uint32_t aH = stg + a_off;
        uint32_t aL = stg + TILE_BYTES + a_off;
        uint32_t bH = stg + 2 * TILE_BYTES + b_off;
        uint32_t bL = stg + 3 * TILE_BYTES + b_off;

#pragma unroll
        for (int ks = 0; ks < 2; ks++) {
            uint32_t ko = ks * 32;
            uint32_t ah[4][4], al[4][4], bh[4][2], bl[4][2];
#pragma unroll
            for (int mt = 0; mt < 4; mt++) {
                ldm_x4(ah[mt], aH + ko + mt * 16 * TSTRIDE);
                ldm_x4(al[mt], aL + ko + mt * 16 * TSTRIDE);
            }
#pragma unroll
            for (int bp = 0; bp < 2; bp++) {
                uint32_t r[4];
                ldm_x4(r, bH + ko + bp * 16 * TSTRIDE);
                bh[2 * bp][0] = r[0]; bh[2 * bp][1] = r[1];
                bh[2 * bp + 1][0] = r[2]; bh[2 * bp + 1][1] = r[3];
                ldm_x4(r, bL + ko + bp * 16 * TSTRIDE);
                bl[2 * bp][0] = r[0]; bl[2 * bp][1] = r[1];
                bl[2 * bp + 1][0] = r[2]; bl[2 * bp + 1][1] = r[3];
            }
#pragma unroll
            for (int mt = 0; mt < 4; mt++)
#pragma unroll
                for (int nt = 0; nt < 4; nt++) {
                    mma_bf16(acc[mt][nt], ah[mt], bh[nt]);
                    mma_bf16(acc[mt][nt], ah[mt], bl[nt]);
                    mma_bf16(acc[mt][nt], al[mt], bh[nt]);
                }
        }
        __syncthreads();
    }

    int gid = lane >> 2, tg = lane & 3;
#pragma unroll
    for (int mt = 0; mt < 4; mt++) {
#pragma unroll
        for (int nt = 0; nt < 4; nt++) {
            int row = m0 + warp_m * 64 + mt * 16 + gid;
            int col = n0 + warp_n * 32 + nt * 8 + tg * 2;
            *(float2*)(Cm + (size_t)row * N + col) =
                make_float2(acc[mt][nt][0], acc[mt][nt][1]);
            *(float2*)(Cm + (size_t)(row + 8) * N + col) =
                make_float2(acc[mt][nt][2], acc[mt][nt][3]);
        }
    }
}

// ---------------- Q/K rmsnorm + RoPE + gain*scale -> bf16 hi/lo ---------------------
__global__ void __launch_bounds__(256) k_qkpost(const float* __restrict__ qg) {
    int gwarp = (blockIdx.x * 256 + threadIdx.x) >> 5;
    int lane = threadIdx.x & 31;
    const int NQ = B_ * T_ * H_;
    const int NK = B_ * T_ * HKV_;
    if (gwarp < NQ) {
        int h = gwarp % H_;
        int bt = gwarp / H_;
        int t = bt % T_, b = bt / T_;
        const float* src = g_qkv + (size_t)bt * QKVN_ + h * HD_;
        float v0 = src[lane], v1 = src[lane + 32], v2 = src[lane + 64], v3 = src[lane + 96];
        float ss = v0 * v0 + v1 * v1 + v2 * v2 + v3 * v3;
#pragma unroll
        for (int o = 16; o; o >>= 1) ss += __shfl_xor_sync(0xffffffffu, ss, o);
        float sc = rsqrtf(ss * (1.0f / HD_) + EPS_);
        v0 *= sc; v1 *= sc; v2 *= sc; v3 *= sc;
        float c0 = g_cos[t * 64 + lane],      s0 = g_sin[t * 64 + lane];
        float c1 = g_cos[t * 64 + 32 + lane], s1 = g_sin[t * 64 + 32 + lane];
        float gn = qg[h] * SCALE_;     // fold softmax scale into Q
        float r0 = (v0 * c0 - v2 * s0) * gn;
        float r1 = (v1 * c1 - v3 * s1) * gn;
        float r2 = (v2 * c0 + v0 * s0) * gn;
        float r3 = (v3 * c1 + v1 * s1) * gn;
        size_t base = ((size_t)(b * H_ + h) * T_ + t) * HD_;
        __nv_bfloat16 hh, ll;
        bsplit(r0, hh, ll); g_qh[base + lane] = hh;      g_ql[base + lane] = ll;
        bsplit(r1, hh, ll); g_qh[base + lane + 32] = hh; g_ql[base + lane + 32] = ll;
        bsplit(r2, hh, ll); g_qh[base + lane + 64] = hh; g_ql[base + lane + 64] = ll;
        bsplit(r3, hh, ll); g_qh[base + lane + 96] = hh; g_ql[base + lane + 96] = ll;
    } else if (gwarp < NQ + NK) {
        int w = gwarp - NQ;
        int g = w % HKV_;
        int bt = w / HKV_;
        int t = bt % T_, b = bt / T_;
        const float* src = g_qkv + (size_t)bt * QKVN_ + C_ + g * HD_;
        float v0 = src[lane], v1 = src[lane + 32], v2 = src[lane + 64], v3 = src[lane + 96];
        float ss = v0 * v0 + v1 * v1 + v2 * v2 + v3 * v3;
#pragma unroll
        for (int o = 16; o; o >>= 1) ss += __shfl_xor_sync(0xffffffffu, ss, o);
        float sc = rsqrtf(ss * (1.0f / HD_) + EPS_);
        v0 *= sc; v1 *= sc; v2 *= sc; v3 *= sc;
        float c0 = g_cos[t * 64 + lane],      s0 = g_sin[t * 64 + lane];
        float c1 = g_cos[t * 64 + 32 + lane], s1 = g_sin[t * 64 + 32 + lane];
        float r0 = v0 * c0 - v2 * s0;
        float r1 = v1 * c1 - v3 * s1;
        float r2 = v2 * c0 + v0 * s0;
        float r3 = v3 * c1 + v1 * s1;
        size_t base = ((size_t)(b * HKV_ + g) * T_ + t) * HD_;
        __nv_bfloat16 hh, ll;
        bsplit(r0, hh, ll); g_kh[base + lane] = hh;      g_kl[base + lane] = ll;
        bsplit(r1, hh, ll); g_kh[base + lane + 32] = hh; g_kl[base + lane + 32] = ll;
        bsplit(r2, hh, ll); g_kh[base + lane + 64] = hh; g_kl[base + lane + 64] = ll;
        bsplit(r3, hh, ll); g_kh[base + lane + 96] = hh; g_kl[base + lane + 96] = ll;
    }
}

// ---------------- V transpose + split: [t][hd] f32 -> [hd][t] bf16 hi/lo -----------
__global__ void __launch_bounds__(256) k_vt() {
    __shared__ float vs[64][129];
    int t0 = blockIdx.x * 64;
    int g = blockIdx.y, b = blockIdx.z;
    int tid = threadIdx.x;
#pragma unroll
    for (int s = 0; s < 8; s++) {
        int c = tid + s * 256;
        int r = c >> 5, q = (c & 31) * 4;
        const float* src = g_qkv + (size_t)(b * T_ + t0 + r) * QKVN_ + C_ + KVD_ + g * HD_ + q;
        float4 v = *(const float4*)src;
        vs[r][q] = v.x; vs[r][q + 1] = v.y; vs[r][q + 2] = v.z; vs[r][q + 3] = v.w;
    }
    __syncthreads();
    int hd = tid >> 1, half = tid & 1;
    __align__(16) __nv_bfloat16 hb[32], lb[32];
#pragma unroll
    for (int j = 0; j < 32; j++)
        bsplit(vs[half * 32 + j][hd], hb[j], lb[j]);
    size_t dst = ((size_t)(b * HKV_ + g) * HD_ + hd) * T_ + t0 + half * 32;
#pragma unroll
    for (int q = 0; q < 4; q++) {
        *(uint4*)(g_vth + dst + q * 8) = *(uint4*)(hb + q * 8);
        *(uint4*)(g_vtl + dst + q * 8) = *(uint4*)(lb + q * 8);
    }
}

// ---------------- tensor-core causal flash attention -------------------------------
// 64 q-rows/block, 64 keys/tile, 4 warps. 3-term split QK^T and PV.
#define FQSTR 272
#define FVSTR 144
#define OFF_QH 0
#define OFF_QL 17408
#define OFF_KH 34816
#define OFF_KL 52224
#define OFF_VH 69632
#define OFF_VL 88064
#define FT_SMEM 106496

__global__ void __launch_bounds__(128) k_flash_t() {
    extern __shared__ char smf[];
    uint32_t sb = smem_u32(smf);
    int tid = threadIdx.x, wid = tid >> 5, lane = tid & 31;
    int qt = blockIdx.x, h = blockIdx.y, b = blockIdx.z, g = h >> 2;
    int q0 = qt * 64;

    const __nv_bfloat16* Qh = g_qh + ((size_t)(b * H_ + h) * T_ + q0) * HD_;
    const __nv_bfloat16* Ql = g_ql + ((size_t)(b * H_ + h) * T_ + q0) * HD_;
    const __nv_bfloat16* Kh = g_kh + (size_t)(b * HKV_ + g) * T_ * HD_;
    const __nv_bfloat16* Kl = g_kl + (size_t)(b * HKV_ + g) * T_ * HD_;
    const __nv_bfloat16* Vh = g_vth + (size_t)(b * HKV_ + g) * HD_ * T_;
    const __nv_bfloat16* Vl = g_vtl + (size_t)(b * HKV_ + g) * HD_ * T_;

    // Q tiles -> smem (once)
#pragma unroll
    for (int s = 0; s < 8; s++) {
        int c = tid + s * 128;
        int r = c >> 4, q = c & 15;
        cpa16(sb + OFF_QH + r * FQSTR + q * 16, Qh + (size_t)r * HD_ + q * 8);
        cpa16(sb + OFF_QL + r * FQSTR + q * 16, Ql + (size_t)r * HD_ + q * 8);
    }
    auto load_kv = [&](int ks) {
        int k0 = ks * 64;
#pragma unroll
        for (int s = 0; s < 8; s++) {
            int c = tid + s * 128;
            int r = c >> 4, q = c & 15;
            cpa16(sb + OFF_KH + r * FQSTR + q * 16, Kh + (size_t)(k0 + r) * HD_ + q * 8);
            cpa16(sb + OFF_KL + r * FQSTR + q * 16, Kl + (size_t)(k0 + r) * HD_ + q * 8);
            int rv = c >> 3, qv = c & 7;
            cpa16(sb + OFF_VH + rv * FVSTR + qv * 16, Vh + (size_t)rv * T_ + k0 + qv * 8);
            cpa16(sb + OFF_VL + rv * FVSTR + qv * 16, Vl + (size_t)rv * T_ + k0 + qv * 8);
        }
    };
    load_kv(0);
    cpa_commit();
    cpa_wait0();
    __syncthreads();

    float m0 = -INFINITY, m1 = -INFINITY, l0 = 0.f, l1 = 0.f;
    float oacc[16][4] = {};

    uint32_t qa = (uint32_t)(wid * 16 + (lane & 15)) * FQSTR + ((lane >> 4) << 4);
    uint32_t kb = (uint32_t)((lane & 7) + ((lane & 16) >> 1)) * FQSTR + ((lane & 8) << 1);
    uint32_t vb = (uint32_t)((lane & 7) + ((lane & 16) >> 1)) * FVSTR + ((lane & 8) << 1);

    for (int ks = 0; ks <= qt; ks++) {
        // ---- S = Q @ K^T (3-term split), pre-scaled ----
        float sacc[8][4] = {};
#pragma unroll
        for (int kc = 0; kc < 8; kc++) {
            uint32_t qh4[4], ql4[4];
            ldm_x4(qh4, sb + OFF_QH + qa + kc * 32);
            ldm_x4(ql4, sb + OFF_QL + qa + kc * 32);
#pragma unroll
            for (int pr = 0; pr < 4; pr++) {
                uint32_t kh4[4], kl4[4];
                ldm_x4(kh4, sb + OFF_KH + kb + pr * 16 * FQSTR + kc * 32);
                ldm_x4(kl4, sb + OFF_KL + kb + pr * 16 * FQSTR + kc * 32);
                mma_bf16(sacc[2 * pr],     qh4, kh4);
                mma_bf16(sacc[2 * pr],     qh4, kl4);
                mma_bf16(sacc[2 * pr],     ql4, kh4);
                mma_bf16(sacc[2 * pr + 1], qh4, kh4 + 2);
                mma_bf16(sacc[2 * pr + 1], qh4, kl4 + 2);
                mma_bf16(sacc[2 * pr + 1], ql4, kh4 + 2);
            }
        }

        // ---- causal mask on diagonal tile ----
        if (ks == qt) {
            int r0 = wid * 16 + (lane >> 2);
#pragma unroll
            for (int nt = 0; nt < 8; nt++) {
                int c0 = nt * 8 + (lane & 3) * 2;
                if (c0     > r0)     sacc[nt][0] = -INFINITY;
                if (c0 + 1 > r0)     sacc[nt][1] = -INFINITY;
                if (c0     > r0 + 8) sacc[nt][2] = -INFINITY;
                if (c0 + 1 > r0 + 8) sacc[nt][3] = -INFINITY;
            }
        }

        // ---- online softmax (rows r0=lane>>2 and r0+8) ----
        float mt0 = -INFINITY, mt1 = -INFINITY;
#pragma unroll
        for (int nt = 0; nt < 8; nt++) {
            mt0 = fmaxf(mt0, fmaxf(sacc[nt][0], sacc[nt][1]));
            mt1 = fmaxf(mt1, fmaxf(sacc[nt][2], sacc[nt][3]));
        }
        mt0 = fmaxf(mt0, __shfl_xor_sync(0xffffffffu, mt0, 1));
        mt0 = fmaxf(mt0, __shfl_xor_sync(0xffffffffu, mt0, 2));
        mt1 = fmaxf(mt1, __shfl_xor_sync(0xffffffffu, mt1, 1));
        mt1 = fmaxf(mt1, __shfl_xor_sync(0xffffffffu, mt1, 2));
        float mn0 = fmaxf(m0, mt0), mn1 = fmaxf(m1, mt1);
        float al0 = __expf(m0 - mn0), al1 = __expf(m1 - mn1);
        m0 = mn0; m1 = mn1;
        float ls0 = 0.f, ls1 = 0.f;
#pragma unroll
        for (int nt = 0; nt < 8; nt++) {
            sacc[nt][0] = __expf(sacc[nt][0] - mn0);
            sacc[nt][1] = __expf(sacc[nt][1] - mn0);
            sacc[nt][2] = __expf(sacc[nt][2] - mn1);
            sacc[nt][3] = __expf(sacc[nt][3] - mn1);
            ls0 += sacc[nt][0] + sacc[nt][1];
            ls1 += sacc[nt][2] + sacc[nt][3];
        }
        ls0 += __shfl_xor_sync(0xffffffffu, ls0, 1);
        ls0 += __shfl_xor_sync(0xffffffffu, ls0, 2);
        ls1 += __shfl_xor_sync(0xffffffffu, ls1, 1);
        ls1 += __shfl_xor_sync(0xffffffffu, ls1, 2);
        l0 = l0 * al0 + ls0;
        l1 = l1 * al1 + ls1;
#pragma unroll
        for (int nt = 0; nt < 16; nt++) {
            oacc[nt][0] *= al0; oacc[nt][1] *= al0;
            oacc[nt][2] *= al1; oacc[nt][3] *= al1;
        }

        // ---- O += P @ V (3-term split); S acc fragments repack as A fragments ----
#pragma unroll
        for (int kc = 0; kc < 4; kc++) {
            uint32_t pah[4], pal[4];
            float* sA = sacc[2 * kc];
            float* sB = sacc[2 * kc + 1];
            __nv_bfloat162 t0v = __floats2bfloat162_rn(sA[0], sA[1]);
            __nv_bfloat162 t1v = __floats2bfloat162_rn(sA[2], sA[3]);
            __nv_bfloat162 t2v = __floats2bfloat162_rn(sB[0], sB[1]);
            __nv_bfloat162 t3v = __floats2bfloat162_rn(sB[2], sB[3]);
            pah[0] = *(uint32_t*)&t0v; pah[1] = *(uint32_t*)&t1v;
            pah[2] = *(uint32_t*)&t2v; pah[3] = *(uint32_t*)&t3v;
            __nv_bfloat162 u0 = __floats2bfloat162_rn(sA[0] - __bfloat162float(t0v.x), sA[1] - __bfloat162float(t0v.y));
            __nv_bfloat162 u1 = __floats2bfloat162_rn(sA[2] - __bfloat162float(t1v.x), sA[3] - __bfloat162float(t1v.y));
            __nv_bfloat162 u2 = __floats2bfloat162_rn(sB[0] - __bfloat162float(t2v.x), sB[1] - __bfloat162float(t2v.y));
            __nv_bfloat162 u3 = __floats2bfloat162_rn(sB[2] - __bfloat162float(t3v.x), sB[3] - __bfloat162float(t3v.y));
            pal[0] = *(uint32_t*)&u0; pal[1] = *(uint32_t*)&u1;
            pal[2] = *(uint32_t*)&u2; pal[3] = *(uint32_t*)&u3;
#pragma unroll
            for (int pr = 0; pr < 8; pr++) {
                uint32_t vh4[4], vl4[4];
                ldm_x4(vh4, sb + OFF_VH + vb + pr * 16 * FVSTR + kc * 32);
                ldm_x4(vl4, sb + OFF_VL + vb + pr * 16 * FVSTR + kc * 32);
                mma_bf16(oacc[2 * pr],     pah, vh4);
                mma_bf16(oacc[2 * pr],     pah, vl4);
                mma_bf16(oacc[2 * pr],     pal, vh4);
                mma_bf16(oacc[2 * pr + 1], pah, vh4 + 2);
                mma_bf16(oacc[2 * pr + 1], pah, vl4 + 2);
                mma_bf16(oacc[2 * pr + 1], pal, vh4 + 2);
            }
        }
        __syncthreads();
        if (ks < qt) {
            load_kv(ks + 1);
            cpa_commit();
            cpa_wait0();
            __syncthreads();
        }
    }

    // ---- epilogue: normalize, split bf16, write GEMM-A operands ----
    float inv0 = 1.0f / l0, inv1 = 1.0f / l1;
    int r0g = q0 + wid * 16 + (lane >> 2);
    size_t base0 = ((size_t)(b * T_) + r0g) * C_ + h * HD_ + (lane & 3) * 2;
    size_t base1 = base0 + (size_t)8 * C_;
#pragma unroll
    for (int nt = 0; nt < 16; nt++) {
        float v0 = oacc[nt][0] * inv0, v1 = oacc[nt][1] * inv0;
        __nv_bfloat162 hh = __floats2bfloat162_rn(v0, v1);
        __nv_bfloat162 ll = __floats2bfloat162_rn(v0 - __bfloat162float(hh.x), v1 - __bfloat162float(hh.y));
        *(uint32_t*)(g_ah + base0 + nt * 8) = *(uint32_t*)&hh;
        *(uint32_t*)(g_al + base0 + nt * 8) = *(uint32_t*)&ll;
        v0 = oacc[nt][2] * inv1; v1 = oacc[nt][3] * inv1;
        hh = __floats2bfloat162_rn(v0, v1);
        ll = __floats2bfloat162_rn(v0 - __bfloat162float(hh.x), v1 - __bfloat162float(hh.y));
        *(uint32_t*)(g_ah + base1 + nt * 8) = *(uint32_t*)&hh;
        *(uint32_t*)(g_al + base1 + nt * 8) = *(uint32_t*)&ll;
    }
}

// ---------------- launcher ----------------------------------------------------------
extern "C" void kernel_launch(void* const* d_in, const int* in_sizes, int n_in,
                              void* d_out, int out_size) {
    (void)in_sizes; (void)n_in; (void)out_size;
    const float* x      = (const float*)d_in[0];
    const float* w_qkv  = (const float*)d_in[1];
    const float* w_proj = (const float*)d_in[2];
    const float* q_gain = (const float*)d_in[3];
    float* out = (float*)d_out;

    __nv_bfloat16 *p_ah, *p_al, *p_bh1, *p_bl1, *p_bh2, *p_bl2;
    float* p_qkv;
    cudaGetSymbolAddress((void**)&p_ah, g_ah);
    cudaGetSymbolAddress((void**)&p_al, g_al);
    cudaGetSymbolAddress((void**)&p_bh1, g_bh1);
    cudaGetSymbolAddress((void**)&p_bl1, g_bl1);
    cudaGetSymbolAddress((void**)&p_bh2, g_bh2);
    cudaGetSymbolAddress((void**)&p_bl2, g_bl2);
    cudaGetSymbolAddress((void**)&p_qkv, g_qkv);

    cudaFuncSetAttribute(k_gemm_bf16, cudaFuncAttributeMaxDynamicSharedMemorySize, GSMEM);
    cudaFuncSetAttribute(k_flash_t, cudaFuncAttributeMaxDynamicSharedMemorySize, FT_SMEM);

    k_rope<<<T_, 64>>>();
    k_rmsnorm<<<M_ROWS, 256>>>(x);

    dim3 gw1(QKVN_ / 32, C_ / 32);
    k_splitw<<<gw1, 256>>>(w_qkv, p_bh1, p_bl1, C_, QKVN_);
    dim3 gw2(C_ / 32, C_ / 32);
    k_splitw<<<gw2, 256>>>(w_proj, p_bh2, p_bl2, C_, C_);

    dim3 g1(QKVN_ / 128, M_ROWS / 128);
    k_gemm_bf16<<<g1, 256, GSMEM>>>(p_ah, p_al, p_bh1, p_bl1, p_qkv, M_ROWS, QKVN_, C_);

    int njobs = B_ * T_ * H_ + B_ * T_ * HKV_;   // Q + K warps
    k_qkpost<<<njobs / 8, 256>>>(q_gain);
    dim3 gv(T_ / 64, HKV_, B_);
    k_vt<<<gv, 256>>>();

    dim3 gf(T_ / 64, H_, B_);
    k_flash_t<<<gf, 128, FT_SMEM>>>();

    dim3 g2(C_ / 128, M_ROWS / 128);
    k_gemm_bf16<<<g2, 256, GSMEM>>>(p_ah, p_al, p_bh2, p_bl2, out, M_ROWS, C_, C_);
}